// round 7
// baseline (speedup 1.0000x reference)
#include <cuda_runtime.h>
#include <math.h>

#define BB 2
#define QQ 2048
#define FF 1538
#define CH 514          // faces per smem chunk (3 chunks cover 1538)

__device__ float g_res[BB * QQ];
__device__ float g_partial[BB];
__device__ unsigned int g_done = 0;

// ---------------------------------------------------------------------------
// fast helpers
// ---------------------------------------------------------------------------
__device__ __forceinline__ float sqrt_approx(float x) {
    float r;
    asm("sqrt.approx.f32 %0, %1;" : "=f"(r) : "f"(x));
    return r;
}

// atan2 via quadrant folding + degree-11 odd minimax poly (|err| ~ 3e-6 on [0,1])
__device__ __forceinline__ float fast_atan2(float y, float x) {
    float ax = fabsf(x), ay = fabsf(y);
    float mx = fmaxf(ax, ay), mn = fminf(ax, ay);
    float t = __fdividef(mn, mx);
    float s = t * t;
    float p =             -0.01172120f;
    p = fmaf(p, s,  0.05265332f);
    p = fmaf(p, s, -0.11643287f);
    p = fmaf(p, s,  0.19354346f);
    p = fmaf(p, s, -0.33262347f);
    p = fmaf(p, s,  0.99997726f);
    float r = p * t;                         // atan(t), t in [0,1]
    if (ay > ax) r = 1.57079632679f - r;
    if (x < 0.0f) r = 3.14159265359f - r;
    return copysignf(r, y);
}

// ---------------------------------------------------------------------------
// Kernel 1: winding numbers + residuals.
// TWO queries per warp (ILP=2) and TWO warps per query pair (face split).
// 128-thread blocks, 4 queries/block -> 1024 blocks.
// ---------------------------------------------------------------------------
__global__ __launch_bounds__(128) void wn_kernel(const float* __restrict__ points,
                                                 const float* __restrict__ tris,
                                                 const float* __restrict__ occ) {
    __shared__ float st[CH * 12];
    __shared__ float sacc[8];     // [warp*2 + whichQuery]

    int tid  = threadIdx.x;
    int warp = tid >> 5;          // 0..3
    int lane = tid & 31;
    int pair = warp >> 1;         // query pair 0/1 within block
    int half = warp & 1;          // face-stride half

    int qA = blockIdx.x * 4 + pair * 2;   // 1024 blocks * 4 queries = 4096
    int qB = qA + 1;
    int b  = qA >> 11;                    // batch (uniform per block)

    float pxA = points[qA * 3 + 0], pyA = points[qA * 3 + 1], pzA = points[qA * 3 + 2];
    float pxB = points[qB * 3 + 0], pyB = points[qB * 3 + 1], pzB = points[qB * 3 + 2];

    const float* tb = tris + (size_t)b * FF * 9;

    float accA = 0.0f, accB = 0.0f;
    for (int base = 0; base < FF; base += CH) {
        int nf = min(CH, FF - base);
        __syncthreads();
        // stage: one face per thread, strided (no integer division)
        for (int f = tid; f < nf; f += 128) {
            const float* src = tb + (size_t)(base + f) * 9;
            float* dst = &st[f * 12];
            #pragma unroll
            for (int c = 0; c < 9; c++) dst[c] = src[c];
        }
        __syncthreads();

        for (int f = half * 32 + lane; f < nf; f += 64) {
            const float4* t4 = (const float4*)&st[f * 12];
            float4 v0 = t4[0];   // ax ay az bx
            float4 v1 = t4[1];   // by bz cx cy
            float4 v2 = t4[2];   // cz . . .

            // ----- query A -----
            {
                float ax = v0.x - pxA, ay = v0.y - pyA, az = v0.z - pzA;
                float bx = v0.w - pxA, by = v1.x - pyA, bz = v1.y - pzA;
                float cx = v1.z - pxA, cy = v1.w - pyA, cz = v2.x - pzA;

                float na = sqrt_approx(fmaf(ax, ax, fmaf(ay, ay, az * az)));
                float nb = sqrt_approx(fmaf(bx, bx, fmaf(by, by, bz * bz)));
                float nc = sqrt_approx(fmaf(cx, cx, fmaf(cy, cy, cz * cz)));

                float crx = by * cz - bz * cy;
                float cry = bz * cx - bx * cz;
                float crz = bx * cy - by * cx;

                float num = fmaf(ax, crx, fmaf(ay, cry, az * crz));
                float d01 = fmaf(ax, bx, fmaf(ay, by, az * bz));
                float d12 = fmaf(bx, cx, fmaf(by, cy, bz * cz));
                float d02 = fmaf(ax, cx, fmaf(ay, cy, az * cz));

                float den = fmaf(na * nb, nc, fmaf(d01, nc, fmaf(d02, nb, d12 * na)));
                accA += fast_atan2(num, den);
            }
            // ----- query B -----
            {
                float ax = v0.x - pxB, ay = v0.y - pyB, az = v0.z - pzB;
                float bx = v0.w - pxB, by = v1.x - pyB, bz = v1.y - pzB;
                float cx = v1.z - pxB, cy = v1.w - pyB, cz = v2.x - pzB;

                float na = sqrt_approx(fmaf(ax, ax, fmaf(ay, ay, az * az)));
                float nb = sqrt_approx(fmaf(bx, bx, fmaf(by, by, bz * bz)));
                float nc = sqrt_approx(fmaf(cx, cx, fmaf(cy, cy, cz * cz)));

                float crx = by * cz - bz * cy;
                float cry = bz * cx - bx * cz;
                float crz = bx * cy - by * cx;

                float num = fmaf(ax, crx, fmaf(ay, cry, az * crz));
                float d01 = fmaf(ax, bx, fmaf(ay, by, az * bz));
                float d12 = fmaf(bx, cx, fmaf(by, cy, bz * cz));
                float d02 = fmaf(ax, cx, fmaf(ay, cy, az * cz));

                float den = fmaf(na * nb, nc, fmaf(d01, nc, fmaf(d02, nb, d12 * na)));
                accB += fast_atan2(num, den);
            }
        }
    }

    #pragma unroll
    for (int o = 16; o > 0; o >>= 1) {
        accA += __shfl_xor_sync(0xFFFFFFFFu, accA, o);
        accB += __shfl_xor_sync(0xFFFFFFFFu, accB, o);
    }

    if (lane == 0) {
        sacc[warp * 2 + 0] = accA;
        sacc[warp * 2 + 1] = accB;
    }
    __syncthreads();

    if (tid < 4) {  // tid = local query index 0..3
        int p    = tid >> 1;
        int qloc = tid & 1;
        float tot = sacc[(p * 2 + 0) * 2 + qloc] + sacc[(p * 2 + 1) * 2 + qloc];
        int q = blockIdx.x * 4 + tid;
        float wn = tot * 0.15915494309189535f;   // (2*atan2 sum)/(4*pi)
        g_res[q] = wn - occ[q];
    }
}

// ---------------------------------------------------------------------------
// Kernel 2: robust weighting. 1024 threads/batch.
// Radix-select with an 11-bit first pass (2048 bins) and early small-select
// (<=256 candidates, warp-broadcast rank select). Pass schedule:
//   {shift=21,11b} {shift=13,8b} {shift=5,8b} {shift=0,5b}   (exact fallback)
// ---------------------------------------------------------------------------
__device__ __forceinline__ unsigned int fkey(float f) {
    unsigned int u = __float_as_uint(f);
    return (u & 0x80000000u) ? ~u : (u | 0x80000000u);
}
__device__ __forceinline__ float key_to_float(unsigned int k) {
    unsigned int bits = (k & 0x80000000u) ? (k ^ 0x80000000u) : ~k;
    return __uint_as_float(bits);
}

struct SelShared {
    unsigned int hist[2048];
    unsigned int wtot[32];
    unsigned int bc[3];        // bin, inner k, bin count / result value
    unsigned int cand[256];
    unsigned int ccnt;
};

// k-th smallest (0-indexed) of the QQ keys; 1024 threads required.
__device__ unsigned int radix_select(const unsigned int* keys, SelShared* ss,
                                     int tid, int k) {
    const int shifts[4] = {21, 13, 5, 0};
    const int nbitsv[4] = {11,  8, 8, 5};

    int wid  = tid >> 5;
    int lane = tid & 31;
    unsigned int prefix = 0;

    for (int pass = 0; pass < 4; pass++) {
        int shift = shifts[pass];
        int nb    = nbitsv[pass];
        int nbin  = 1 << nb;

        for (int i = tid; i < nbin; i += 1024) ss->hist[i] = 0;
        if (tid == 0) ss->ccnt = 0;
        __syncthreads();

        unsigned int himask = (pass == 0) ? 0u : (0xFFFFFFFFu << (shift + nb));
        #pragma unroll
        for (int i = tid; i < QQ; i += 1024) {        // 2 iterations
            unsigned int u = keys[i];
            if ((u & himask) == (prefix & himask))
                atomicAdd(&ss->hist[(u >> shift) & (unsigned)(nbin - 1)], 1u);
        }
        __syncthreads();

        // scan: thread owns 1 or 2 bins
        unsigned int c0 = 0, c1 = 0;
        if (nbin > 1024) {
            c0 = ss->hist[2 * tid];
            c1 = ss->hist[2 * tid + 1];
        } else if (tid < nbin) {
            c0 = ss->hist[tid];
        }
        unsigned int mysum = c0 + c1;
        unsigned int v = mysum;
        #pragma unroll
        for (int o = 1; o < 32; o <<= 1) {
            unsigned int y = __shfl_up_sync(0xFFFFFFFFu, v, o);
            if (lane >= o) v += y;
        }
        if (lane == 31) ss->wtot[wid] = v;
        __syncthreads();
        if (wid == 0) {
            unsigned int t0 = ss->wtot[lane];
            unsigned int t  = t0;
            #pragma unroll
            for (int o = 1; o < 32; o <<= 1) {
                unsigned int y = __shfl_up_sync(0xFFFFFFFFu, t, o);
                if (lane >= o) t += y;
            }
            ss->wtot[lane] = t - t0;   // exclusive warp offset
        }
        __syncthreads();

        unsigned int inc = v + ss->wtot[wid];
        unsigned int exc = inc - mysum;
        // thread's bins: bin0 at rank [exc, exc+c0), bin1 at [exc+c0, exc+c0+c1)
        int bin0 = (nbin > 1024) ? (2 * tid) : tid;
        if ((int)exc <= k && k < (int)(exc + c0)) {
            ss->bc[0] = (unsigned int)bin0;
            ss->bc[1] = (unsigned int)(k - (int)exc);
            ss->bc[2] = c0;
        }
        if (nbin > 1024 && (int)(exc + c0) <= k && k < (int)(exc + c0 + c1)) {
            ss->bc[0] = (unsigned int)(bin0 + 1);
            ss->bc[1] = (unsigned int)(k - (int)(exc + c0));
            ss->bc[2] = c1;
        }
        __syncthreads();

        prefix |= (ss->bc[0] << shift);
        k = (int)ss->bc[1];
        unsigned int cnt = ss->bc[2];

        if (shift == 0) return prefix;     // fully resolved

        if (cnt <= 256u) {
            unsigned int hi2 = 0xFFFFFFFFu << shift;
            #pragma unroll
            for (int i = tid; i < QQ; i += 1024) {
                unsigned int u = keys[i];
                if ((u & hi2) == prefix) {
                    unsigned int p = atomicAdd(&ss->ccnt, 1u);
                    ss->cand[p] = u;
                }
            }
            __syncthreads();
            int n = (int)cnt;
            if (tid < n) {
                unsigned int vv = ss->cand[tid];
                int less = 0, eq = 0;
                for (int j = 0; j < n; j++) {
                    unsigned int u = ss->cand[j];   // broadcast LDS
                    less += (u < vv);
                    eq   += (u == vv);
                }
                if (less <= k && k < less + eq) ss->bc[2] = vv;  // unique value
            }
            __syncthreads();
            return ss->bc[2];
        }
        __syncthreads();   // protect bc/ccnt before next-pass writes
    }
    return prefix;
}

__global__ __launch_bounds__(1024) void robust_kernel(float* __restrict__ out) {
    __shared__ float        rs[QQ];
    __shared__ unsigned int keys[QQ];
    __shared__ SelShared    ss;
    __shared__ float        red[32];

    int b   = blockIdx.x;
    int tid = threadIdx.x;

    #pragma unroll
    for (int i = tid; i < QQ; i += 1024) {
        float v = g_res[b * QQ + i];
        rs[i]   = v;
        keys[i] = fkey(v);
    }
    __syncthreads();

    float med = key_to_float(radix_select(keys, &ss, tid, (QQ - 1) / 2));
    __syncthreads();

    #pragma unroll
    for (int i = tid; i < QQ; i += 1024)
        keys[i] = fkey(fabsf(rs[i] - med));
    __syncthreads();

    float mad = key_to_float(radix_select(keys, &ss, tid, (QQ - 1) / 2));

    float scale = (mad / 0.67449f) * 4.6851f;

    float sum = 0.0f;
    #pragma unroll
    for (int i = tid; i < QQ; i += 1024) {
        float r  = rs[i];
        float nr = r / scale;
        float t  = 1.0f - nr * nr;
        float w  = (nr >= 1.0f) ? 0.0f : t * t;
        sum += w * r * r;
    }

    #pragma unroll
    for (int o = 16; o > 0; o >>= 1)
        sum += __shfl_xor_sync(0xFFFFFFFFu, sum, o);
    if ((tid & 31) == 0) red[tid >> 5] = sum;
    __syncthreads();

    if (tid < 32) {
        float s = red[tid];
        #pragma unroll
        for (int o = 16; o > 0; o >>= 1)
            s += __shfl_xor_sync(0xFFFFFFFFu, s, o);
        if (tid == 0) {
            g_partial[b] = s;
            __threadfence();
            unsigned int prev = atomicAdd(&g_done, 1u);
            if (prev == BB - 1) {
                out[0] = 0.5f * (g_partial[0] + g_partial[1]);
                g_done = 0;  // reset for next graph replay
            }
        }
    }
}

extern "C" void kernel_launch(void* const* d_in, const int* in_sizes, int n_in,
                              void* d_out, int out_size) {
    const float* points = (const float*)d_in[0];  // (B,Q,3)
    const float* tris   = (const float*)d_in[1];  // (B,F,3,3)
    const float* occ    = (const float*)d_in[2];  // (B,Q)
    float* out = (float*)d_out;

    wn_kernel<<<(BB * QQ) / 4, 128>>>(points, tris, occ);
    robust_kernel<<<BB, 1024>>>(out);
}

// round 8
// speedup vs baseline: 1.1727x; 1.1727x over previous
#include <cuda_runtime.h>
#include <math.h>

#define BB 2
#define QQ 2048
#define FF 1538
#define CH 514          // faces per smem chunk (3 chunks cover 1538)

__device__ float g_res[BB * QQ];
__device__ float g_partial[BB];
__device__ unsigned int g_done = 0;

// ---------------------------------------------------------------------------
// packed f32x2 helpers (Blackwell)
// ---------------------------------------------------------------------------
typedef unsigned long long u64_t;

__device__ __forceinline__ u64_t pk2(float lo, float hi) {
    u64_t r; asm("mov.b64 %0, {%1, %2};" : "=l"(r) : "f"(lo), "f"(hi)); return r;
}
__device__ __forceinline__ void upk2(u64_t v, float& lo, float& hi) {
    asm("mov.b64 {%0, %1}, %2;" : "=f"(lo), "=f"(hi) : "l"(v));
}
__device__ __forceinline__ u64_t f2sub(u64_t a, u64_t b) {
    u64_t r; asm("sub.rn.f32x2 %0, %1, %2;" : "=l"(r) : "l"(a), "l"(b)); return r;
}
__device__ __forceinline__ u64_t f2mul(u64_t a, u64_t b) {
    u64_t r; asm("mul.rn.f32x2 %0, %1, %2;" : "=l"(r) : "l"(a), "l"(b)); return r;
}
__device__ __forceinline__ u64_t f2fma(u64_t a, u64_t b, u64_t c) {
    u64_t r; asm("fma.rn.f32x2 %0, %1, %2, %3;" : "=l"(r) : "l"(a), "l"(b), "l"(c)); return r;
}

__device__ __forceinline__ float sqrt_approx(float x) {
    float r; asm("sqrt.approx.f32 %0, %1;" : "=f"(r) : "f"(x)); return r;
}
__device__ __forceinline__ float rcp_approx(float x) {
    float r; asm("rcp.approx.f32 %0, %1;" : "=f"(r) : "f"(x)); return r;
}

// ---------------------------------------------------------------------------
// Kernel 1: winding numbers + residuals.
// TWO queries per warp, fully packed in f32x2 (1 instr drives both queries).
// TWO warps per query pair (face split). 128-thread blocks -> 1024 blocks.
// ---------------------------------------------------------------------------
__global__ __launch_bounds__(128) void wn_kernel(const float* __restrict__ points,
                                                 const float* __restrict__ tris,
                                                 const float* __restrict__ occ) {
    __shared__ float st[CH * 12];
    __shared__ float sacc[8];     // [warp*2 + whichQuery]

    int tid  = threadIdx.x;
    int warp = tid >> 5;          // 0..3
    int lane = tid & 31;
    int pair = warp >> 1;         // query pair 0/1 within block
    int half = warp & 1;          // face-stride half

    int qA = blockIdx.x * 4 + pair * 2;   // 1024 blocks * 4 queries = 4096
    int qB = qA + 1;
    int b  = qA >> 11;                    // batch (uniform per block)

    u64_t Px = pk2(points[qA * 3 + 0], points[qB * 3 + 0]);
    u64_t Py = pk2(points[qA * 3 + 1], points[qB * 3 + 1]);
    u64_t Pz = pk2(points[qA * 3 + 2], points[qB * 3 + 2]);

    // packed atan poly coefficients (degree-11 odd minimax, |err|~3e-6)
    const u64_t C5 = pk2(-0.01172120f, -0.01172120f);
    const u64_t C4 = pk2( 0.05265332f,  0.05265332f);
    const u64_t C3 = pk2(-0.11643287f, -0.11643287f);
    const u64_t C2 = pk2( 0.19354346f,  0.19354346f);
    const u64_t C1 = pk2(-0.33262347f, -0.33262347f);
    const u64_t C0 = pk2( 0.99997726f,  0.99997726f);

    const float* tb = tris + (size_t)b * FF * 9;

    float accA = 0.0f, accB = 0.0f;
    for (int base = 0; base < FF; base += CH) {
        int nf = min(CH, FF - base);
        __syncthreads();
        for (int f = tid; f < nf; f += 128) {
            const float* src = tb + (size_t)(base + f) * 9;
            float* dst = &st[f * 12];
            #pragma unroll
            for (int c = 0; c < 9; c++) dst[c] = src[c];
        }
        __syncthreads();

        for (int f = half * 32 + lane; f < nf; f += 64) {
            const float4* t4 = (const float4*)&st[f * 12];
            float4 v0 = t4[0];   // ax ay az bx
            float4 v1 = t4[1];   // by bz cx cy
            float4 v2 = t4[2];   // cz . . .

            // centered vertices, packed across the two queries
            u64_t a_x = f2sub(pk2(v0.x, v0.x), Px);
            u64_t a_y = f2sub(pk2(v0.y, v0.y), Py);
            u64_t a_z = f2sub(pk2(v0.z, v0.z), Pz);
            u64_t b_x = f2sub(pk2(v0.w, v0.w), Px);
            u64_t b_y = f2sub(pk2(v1.x, v1.x), Py);
            u64_t b_z = f2sub(pk2(v1.y, v1.y), Pz);
            u64_t c_x = f2sub(pk2(v1.z, v1.z), Px);
            u64_t c_y = f2sub(pk2(v1.w, v1.w), Py);
            u64_t c_z = f2sub(pk2(v2.x, v2.x), Pz);

            u64_t na2 = f2fma(a_x, a_x, f2fma(a_y, a_y, f2mul(a_z, a_z)));
            u64_t nb2 = f2fma(b_x, b_x, f2fma(b_y, b_y, f2mul(b_z, b_z)));
            u64_t nc2 = f2fma(c_x, c_x, f2fma(c_y, c_y, f2mul(c_z, c_z)));

            float sl, sh;
            upk2(na2, sl, sh);
            u64_t na = pk2(sqrt_approx(sl), sqrt_approx(sh));
            upk2(nb2, sl, sh);
            u64_t nb = pk2(sqrt_approx(sl), sqrt_approx(sh));
            upk2(nc2, sl, sh);
            u64_t nc = pk2(sqrt_approx(sl), sqrt_approx(sh));

            u64_t crx = f2sub(f2mul(b_y, c_z), f2mul(b_z, c_y));
            u64_t cry = f2sub(f2mul(b_z, c_x), f2mul(b_x, c_z));
            u64_t crz = f2sub(f2mul(b_x, c_y), f2mul(b_y, c_x));

            u64_t num = f2fma(a_x, crx, f2fma(a_y, cry, f2mul(a_z, crz)));
            u64_t d01 = f2fma(a_x, b_x, f2fma(a_y, b_y, f2mul(a_z, b_z)));
            u64_t d12 = f2fma(b_x, c_x, f2fma(b_y, c_y, f2mul(b_z, c_z)));
            u64_t d02 = f2fma(a_x, c_x, f2fma(a_y, c_y, f2mul(a_z, c_z)));

            u64_t den = f2fma(f2mul(na, nb), nc,
                        f2fma(d01, nc, f2fma(d02, nb, f2mul(d12, na))));

            // atan2(num, den): scalar quadrant fold, packed polynomial
            float nA, nB, dA, dB;
            upk2(num, nA, nB);
            upk2(den, dA, dB);

            float axA = fabsf(dA), ayA = fabsf(nA);
            float axB = fabsf(dB), ayB = fabsf(nB);
            float mxA = fmaxf(axA, ayA), mnA = fminf(axA, ayA);
            float mxB = fmaxf(axB, ayB), mnB = fminf(axB, ayB);
            float tA = mnA * rcp_approx(mxA);
            float tB = mnB * rcp_approx(mxB);

            u64_t t2 = pk2(tA, tB);
            u64_t s2 = f2mul(t2, t2);
            u64_t p  = f2fma(C5, s2, C4);
            p = f2fma(p, s2, C3);
            p = f2fma(p, s2, C2);
            p = f2fma(p, s2, C1);
            p = f2fma(p, s2, C0);
            u64_t r2 = f2mul(p, t2);

            float rA, rB;
            upk2(r2, rA, rB);
            if (ayA > axA) rA = 1.57079632679f - rA;
            if (dA < 0.0f) rA = 3.14159265359f - rA;
            accA += copysignf(rA, nA);
            if (ayB > axB) rB = 1.57079632679f - rB;
            if (dB < 0.0f) rB = 3.14159265359f - rB;
            accB += copysignf(rB, nB);
        }
    }

    #pragma unroll
    for (int o = 16; o > 0; o >>= 1) {
        accA += __shfl_xor_sync(0xFFFFFFFFu, accA, o);
        accB += __shfl_xor_sync(0xFFFFFFFFu, accB, o);
    }

    if (lane == 0) {
        sacc[warp * 2 + 0] = accA;
        sacc[warp * 2 + 1] = accB;
    }
    __syncthreads();

    if (tid < 4) {  // tid = local query index 0..3
        int p    = tid >> 1;
        int qloc = tid & 1;
        float tot = sacc[(p * 2 + 0) * 2 + qloc] + sacc[(p * 2 + 1) * 2 + qloc];
        int q = blockIdx.x * 4 + tid;
        float wn = tot * 0.15915494309189535f;   // (2*atan2 sum)/(4*pi)
        g_res[q] = wn - occ[q];
    }
}

// ---------------------------------------------------------------------------
// Kernel 2: robust weighting (R6 version — proven 10.3us). 1024 threads/batch.
// 8-bit radix-select with early-exit small-select (<=64 candidates).
// ---------------------------------------------------------------------------
__device__ __forceinline__ unsigned int fkey(float f) {
    unsigned int u = __float_as_uint(f);
    return (u & 0x80000000u) ? ~u : (u | 0x80000000u);
}
__device__ __forceinline__ float key_to_float(unsigned int k) {
    unsigned int bits = (k & 0x80000000u) ? (k ^ 0x80000000u) : ~k;
    return __uint_as_float(bits);
}

struct SelShared {
    unsigned int hist[256];
    unsigned int wtot[8];
    unsigned int bc[3];      // bin, new k, bin count / result value
    unsigned int cand[64];
    unsigned int ccnt;
};

__device__ unsigned int radix_select(const unsigned int* keys, SelShared* ss,
                                     int tid, int k) {
    int wid  = tid >> 5;
    int lane = tid & 31;
    unsigned int prefix = 0;

    for (int shift = 24; shift >= 0; shift -= 8) {
        if (tid < 256) ss->hist[tid] = 0;
        if (tid == 0)  ss->ccnt = 0;
        __syncthreads();

        unsigned int hi = (shift == 24) ? 0u : (0xFFFFFFFFu << (shift + 8));
        #pragma unroll
        for (int i = tid; i < QQ; i += 1024) {
            unsigned int u = keys[i];
            if ((u & hi) == prefix) atomicAdd(&ss->hist[(u >> shift) & 255u], 1u);
        }
        __syncthreads();

        if (tid < 256) {
            unsigned int cnt = ss->hist[tid];
            unsigned int v   = cnt;
            #pragma unroll
            for (int o = 1; o < 32; o <<= 1) {
                unsigned int y = __shfl_up_sync(0xFFFFFFFFu, v, o);
                if (lane >= o) v += y;
            }
            if (lane == 31) ss->wtot[wid] = v;
            __syncthreads();

            if (wid == 0 && lane < 8) {
                unsigned int t0 = ss->wtot[lane];
                unsigned int t  = t0;
                #pragma unroll
                for (int o = 1; o < 8; o <<= 1) {
                    unsigned int y = __shfl_up_sync(0x000000FFu, t, o);
                    if (lane >= o) t += y;
                }
                ss->wtot[lane] = t - t0;
            }
            __syncthreads();

            unsigned int inc = v + ss->wtot[wid];
            unsigned int exc = inc - cnt;
            if ((int)exc <= k && k < (int)inc) {
                ss->bc[0] = (unsigned int)tid;
                ss->bc[1] = (unsigned int)(k - (int)exc);
                ss->bc[2] = cnt;
            }
        } else {
            __syncthreads();
            __syncthreads();
        }
        __syncthreads();

        prefix |= (ss->bc[0] << shift);
        k = (int)ss->bc[1];
        unsigned int cnt = ss->bc[2];

        if (shift > 0 && cnt <= 64u) {
            unsigned int hi2 = 0xFFFFFFFFu << shift;
            #pragma unroll
            for (int i = tid; i < QQ; i += 1024) {
                unsigned int u = keys[i];
                if ((u & hi2) == prefix) {
                    unsigned int p = atomicAdd(&ss->ccnt, 1u);
                    ss->cand[p] = u;
                }
            }
            __syncthreads();
            if (tid < 32) {
                int n = (int)cnt;
                for (int i = tid; i < n; i += 32) {
                    unsigned int v = ss->cand[i];
                    int less = 0, eq = 0;
                    for (int j = 0; j < n; j++) {
                        unsigned int u = ss->cand[j];
                        less += (u < v);
                        eq   += (u == v);
                    }
                    if (less <= k && k < less + eq) ss->bc[2] = v;
                }
            }
            __syncthreads();
            return ss->bc[2];
        }
        __syncthreads();
    }
    return prefix;
}

__global__ __launch_bounds__(1024) void robust_kernel(float* __restrict__ out) {
    __shared__ float        rs[QQ];
    __shared__ unsigned int keys[QQ];
    __shared__ SelShared    ss;
    __shared__ float        red[32];

    int b   = blockIdx.x;
    int tid = threadIdx.x;

    #pragma unroll
    for (int i = tid; i < QQ; i += 1024) {
        float v = g_res[b * QQ + i];
        rs[i]   = v;
        keys[i] = fkey(v);
    }
    __syncthreads();

    float med = key_to_float(radix_select(keys, &ss, tid, (QQ - 1) / 2));
    __syncthreads();

    #pragma unroll
    for (int i = tid; i < QQ; i += 1024)
        keys[i] = fkey(fabsf(rs[i] - med));
    __syncthreads();

    float mad = key_to_float(radix_select(keys, &ss, tid, (QQ - 1) / 2));

    float scale = (mad / 0.67449f) * 4.6851f;

    float sum = 0.0f;
    #pragma unroll
    for (int i = tid; i < QQ; i += 1024) {
        float r  = rs[i];
        float nr = r / scale;
        float t  = 1.0f - nr * nr;
        float w  = (nr >= 1.0f) ? 0.0f : t * t;
        sum += w * r * r;
    }

    #pragma unroll
    for (int o = 16; o > 0; o >>= 1)
        sum += __shfl_xor_sync(0xFFFFFFFFu, sum, o);
    if ((tid & 31) == 0) red[tid >> 5] = sum;
    __syncthreads();

    if (tid < 32) {
        float s = red[tid];
        #pragma unroll
        for (int o = 16; o > 0; o >>= 1)
            s += __shfl_xor_sync(0xFFFFFFFFu, s, o);
        if (tid == 0) {
            g_partial[b] = s;
            __threadfence();
            unsigned int prev = atomicAdd(&g_done, 1u);
            if (prev == BB - 1) {
                out[0] = 0.5f * (g_partial[0] + g_partial[1]);
                g_done = 0;  // reset for next graph replay
            }
        }
    }
}

extern "C" void kernel_launch(void* const* d_in, const int* in_sizes, int n_in,
                              void* d_out, int out_size) {
    const float* points = (const float*)d_in[0];  // (B,Q,3)
    const float* tris   = (const float*)d_in[1];  // (B,F,3,3)
    const float* occ    = (const float*)d_in[2];  // (B,Q)
    float* out = (float*)d_out;

    wn_kernel<<<(BB * QQ) / 4, 128>>>(points, tris, occ);
    robust_kernel<<<BB, 1024>>>(out);
}